// round 1
// baseline (speedup 1.0000x reference)
#include <cuda_runtime.h>
#include <math.h>

// Problem constants (shape-specialized)
#define BB 8
#define CC 3
#define HH 720
#define WW 1280

// Tile config: exact tiling 1280/32=40, 720/40=18
#define TW 32
#define TH 40
#define RPT 5            // rows per thread (8 row-groups * 5 = 40)
#define NTHREADS 256
#define HW2 (TW + 2)     // 34
#define HH2 (TH + 2)     // 42

#define ALPHA_C 0.85f
#define SSIM_C1 0.0001f  // 0.01^2
#define SSIM_C2 0.0009f  // 0.03^2

__device__ double g_acc[2];   // [0] = sum(photo*valid), [1] = sum(valid)

__global__ void pl_init_kernel() {
    g_acc[0] = 0.0;
    g_acc[1] = 0.0;
}

struct HS { float x, y, xx, yy, xy; };

__device__ __forceinline__ HS hsum_row(const float2* row, int tx) {
    HS s;
    s.x = s.y = s.xx = s.yy = s.xy = 0.f;
#pragma unroll
    for (int d = 0; d < 3; d++) {
        float2 v = row[tx + d];
        s.x  += v.x;
        s.y  += v.y;
        s.xx += v.x * v.x;
        s.yy += v.y * v.y;
        s.xy += v.x * v.y;
    }
    return s;
}

__global__ __launch_bounds__(NTHREADS)
void pl_main_kernel(const float* __restrict__ disp,
                    const float* __restrict__ left,
                    const float* __restrict__ right) {
    __shared__ float  s_xs[HH2][HW2];     // raw x_sample per halo pixel
    __shared__ float2 s_xy[HH2][HW2];     // (left, warped) for current channel
    __shared__ float  s_red[2][NTHREADS / 32];

    const int b  = blockIdx.z;
    const int w0 = blockIdx.x * TW;
    const int h0 = blockIdx.y * TH;
    const int tid = threadIdx.x;
    const int tx = tid & 31;        // column within tile
    const int tg = tid >> 5;        // row group 0..7

    // ---- Stage 1: x_sample for the halo tile (computed once) ----
    for (int idx = tid; idx < HH2 * HW2; idx += NTHREADS) {
        int hr = idx / HW2, hc = idx % HW2;
        int hh = h0 - 1 + hr, ww = w0 - 1 + hc;
        float v = 0.f;
        if (hh >= 0 && hh < HH && ww >= 0 && ww < WW) {
            v = (float)ww - disp[(b * HH + hh) * WW + ww];
        }
        s_xs[hr][hc] = v;
    }
    __syncthreads();

    float acc_ssim[RPT], acc_l1[RPT];
#pragma unroll
    for (int k = 0; k < RPT; k++) { acc_ssim[k] = 0.f; acc_l1[k] = 0.f; }

    const int base = tg * RPT;  // halo row index just above this thread's first output row

    for (int c = 0; c < CC; c++) {
        const float* lplane = left  + (size_t)((b * CC + c) * HH) * WW;
        const float* rplane = right + (size_t)((b * CC + c) * HH) * WW;

        // ---- fill (x, warped) halo tile for channel c ----
        for (int idx = tid; idx < HH2 * HW2; idx += NTHREADS) {
            int hr = idx / HW2, hc = idx % HW2;
            int hh = h0 - 1 + hr, ww = w0 - 1 + hc;
            float x = 0.f, y = 0.f;
            if (hh >= 0 && hh < HH && ww >= 0 && ww < WW) {
                x = lplane[hh * WW + ww];
                float xs = s_xs[hr][hc];
                xs = fminf(fmaxf(xs, 0.f), (float)(WW - 1));
                float x0f = floorf(xs);
                float fw  = xs - x0f;
                int i0 = (int)x0f;
                int i1 = min(i0 + 1, WW - 1);
                const float* rr = rplane + hh * WW;
                y = (1.f - fw) * rr[i0] + fw * rr[i1];
            }
            s_xy[hr][hc] = make_float2(x, y);
        }
        __syncthreads();

        // ---- separable 3x3 pooling with rolling horizontal sums ----
        HS a0 = hsum_row(&s_xy[base][0],     tx);
        HS a1 = hsum_row(&s_xy[base + 1][0], tx);
#pragma unroll
        for (int k = 0; k < RPT; k++) {
            HS a2 = hsum_row(&s_xy[base + 2 + k][0], tx);

            float Sx  = a0.x  + a1.x  + a2.x;
            float Sy  = a0.y  + a1.y  + a2.y;
            float Sxx = a0.xx + a1.xx + a2.xx;
            float Syy = a0.yy + a1.yy + a2.yy;
            float Sxy = a0.xy + a1.xy + a2.xy;

            const float inv9 = 1.f / 9.f;
            float mux = Sx * inv9;
            float muy = Sy * inv9;
            float sgx = fmaxf(Sxx * inv9 - mux * mux, 0.f);
            float sgy = fmaxf(Syy * inv9 - muy * muy, 0.f);
            float sxy = Sxy * inv9 - mux * muy;

            float num = (2.f * mux * muy + SSIM_C1) * (2.f * sxy + SSIM_C2);
            float den = (mux * mux + muy * muy + SSIM_C1) * (sgx + sgy + SSIM_C2);
            float ss  = (1.f - num / den) * 0.5f;
            ss = fminf(fmaxf(ss, 0.f), 1.f);
            acc_ssim[k] += ss;

            float2 ctr = s_xy[base + 1 + k][tx + 1];
            acc_l1[k] += fabsf(ctr.x - ctr.y);

            a0 = a1;
            a1 = a2;
        }
        __syncthreads();   // before next channel overwrites s_xy
    }

    // ---- per-pixel photo loss + masked reduction ----
    float psum = 0.f, vsum = 0.f;
#pragma unroll
    for (int k = 0; k < RPT; k++) {
        float xsr = s_xs[base + 1 + k][tx + 1];
        bool valid = (xsr > 0.f) && (xsr < (float)(WW - 1));
        if (valid) {
            float photo = ALPHA_C * (acc_ssim[k] * (1.f / 3.f))
                        + (1.f - ALPHA_C) * (acc_l1[k] * (1.f / 3.f));
            psum += photo;
            vsum += 1.f;
        }
    }

    // warp reduce
#pragma unroll
    for (int off = 16; off > 0; off >>= 1) {
        psum += __shfl_down_sync(0xFFFFFFFFu, psum, off);
        vsum += __shfl_down_sync(0xFFFFFFFFu, vsum, off);
    }
    if (tx == 0) {
        s_red[0][tg] = psum;
        s_red[1][tg] = vsum;
    }
    __syncthreads();
    if (tid == 0) {
        float p = 0.f, v = 0.f;
#pragma unroll
        for (int i = 0; i < NTHREADS / 32; i++) {
            p += s_red[0][i];
            v += s_red[1][i];
        }
        atomicAdd(&g_acc[0], (double)p);
        atomicAdd(&g_acc[1], (double)v);
    }
}

__global__ void pl_finalize_kernel(float* __restrict__ out) {
    out[0] = (float)(g_acc[0] / fmax(g_acc[1], 1.0));
}

extern "C" void kernel_launch(void* const* d_in, const int* in_sizes, int n_in,
                              void* d_out, int out_size) {
    const float* disp  = (const float*)d_in[0];
    const float* left  = (const float*)d_in[1];
    const float* right = (const float*)d_in[2];
    float* out = (float*)d_out;

    pl_init_kernel<<<1, 1>>>();
    dim3 grid(WW / TW, HH / TH, BB);   // 40 x 18 x 8
    pl_main_kernel<<<grid, NTHREADS>>>(disp, left, right);
    pl_finalize_kernel<<<1, 1>>>(out);
}